// round 7
// baseline (speedup 1.0000x reference)
#include <cuda_runtime.h>
#include <cstdint>

#define BB 128
#define SS 32768
#define PP 65536
#define POS_W 5.0f

static_assert((PP % 512) == 0, "blocks must not span batches");

// Scratch (allocation-free rule: __device__ globals).
// g_gt is zero at module load; loss_kernel re-zeroes it every call, so the
// "cleared" invariant holds across graph replays without a dedicated kernel.
__device__ __align__(16) unsigned char g_gt[(size_t)BB * SS];  // 4 MiB
__device__ double g_acc;
__device__ unsigned g_done;
__device__ int g_paths_is64;

// ---------------------------------------------------------------------------
// Kernel 0 (1 warp): detect paths dtype + reset accumulators.
// Values < 2^15, so an int64 layout has every odd 32-bit word == 0; an int32
// layout's odd words are sorted pj values (OR over 1024 of them is nonzero).
// ---------------------------------------------------------------------------
__global__ void detect_kernel(const unsigned* __restrict__ pw) {
    unsigned v = 0;
    for (int j = (int)threadIdx.x * 2 + 1; j < 2048; j += 64)
        v |= pw[j];
#pragma unroll
    for (int o = 16; o > 0; o >>= 1)
        v |= __shfl_xor_sync(0xFFFFFFFFu, v, o);
    if (threadIdx.x == 0) {
        g_paths_is64 = (v == 0u) ? 1 : 0;
        g_acc = 0.0;
        g_done = 0u;
    }
}

// ---------------------------------------------------------------------------
// Kernel 1: scatter. TWO path entries per thread (B*P/2 = 4,194,304 threads).
// pj sorted per batch => is_first == (k==0 || pj[k] != pj[k-1]).
// Entry 2t's prev comes from the lane neighbor's second pj (shuffle); entry
// 2t+1's prev is in-register. Lane 0 loads the single straggler scalar.
// All effective gt writers store 1 => plain byte store, benign race.
// Paths streamed with __ldcs (evict-first) to keep targets/gt rows in L2.
// This kernel is at the DRAM roofline (134 MB of paths for int64).
// ---------------------------------------------------------------------------
__global__ void scatter_kernel(const void* __restrict__ paths_v,
                               const int* __restrict__ targets) {
    unsigned t = blockIdx.x * blockDim.x + threadIdx.x;   // < B*P/2 = 2^22
    unsigned k0 = (t & (PP / 2 - 1)) * 2;   // first entry's step within batch
    unsigned b  = t >> 15;                  // P/2 = 2^15 threads per batch

    int pi0, pj0, pi1, pj1, prev0;
    if (g_paths_is64) {
        const uint4* p = (const uint4*)paths_v;           // 1 entry per uint4
        uint4 v0 = __ldcs(p + (size_t)2 * t);
        uint4 v1 = __ldcs(p + (size_t)2 * t + 1);
        pi0 = (int)v0.x; pj0 = (int)v0.z;                 // low words (LE)
        pi1 = (int)v1.x; pj1 = (int)v1.z;
        prev0 = __shfl_up_sync(0xFFFFFFFFu, pj1, 1);
        if ((threadIdx.x & 31) == 0)
            prev0 = (k0 == 0) ? -1
                  : (int)((const long long*)paths_v)[(size_t)4 * t - 1];
    } else {
        const int4* p = (const int4*)paths_v;             // 2 entries per int4
        int4 v = __ldcs(p + t);
        pi0 = v.x; pj0 = v.y; pi1 = v.z; pj1 = v.w;
        prev0 = __shfl_up_sync(0xFFFFFFFFu, pj1, 1);
        if ((threadIdx.x & 31) == 0)
            prev0 = (k0 == 0) ? -1
                  : ((const int*)paths_v)[(size_t)4 * t - 1];
    }

    const int* trow = targets + b * SS;
    unsigned char* grow = g_gt + b * SS;
    if (pj0 != prev0 && trow[pj0] == 1) grow[pi0] = (unsigned char)1;
    if (pj1 != pj0   && trow[pj1] == 1) grow[pi1] = (unsigned char)1;
}

// ---------------------------------------------------------------------------
// Kernel 2: loss + reduction + finalize + gt re-zero. 8 elements per thread
// (2x float4 preds, 8 gt bytes). loss = 5*gt*softplus(-x)+(1-gt)*softplus(x);
// softplus(x) = max(x,0) + log(1 + exp(-|x|)), MUFU fast-math (arg of log in
// [1,2] -> abs err ~1e-7, negligible vs 1e-3 threshold).
// After reading gt, zeros are stored back, restoring the cleared invariant
// for the next graph replay. Last finished block writes the mean and resets
// the accumulators.
// ---------------------------------------------------------------------------
__global__ void loss_kernel(const float* __restrict__ preds,
                            float* __restrict__ out) {
    unsigned i = blockIdx.x * blockDim.x + threadIdx.x;   // < B*S/8
    float4 p0 = ((const float4*)preds)[(size_t)2 * i];
    float4 p1 = ((const float4*)preds)[(size_t)2 * i + 1];
    uint2 g = ((const uint2*)g_gt)[i];
    ((uint2*)g_gt)[i] = make_uint2(0u, 0u);              // re-zero for next call

    float xv[8] = {p0.x, p0.y, p0.z, p0.w, p1.x, p1.y, p1.z, p1.w};
    unsigned gb[8];
#pragma unroll
    for (int j = 0; j < 4; ++j) { gb[j] = (g.x >> (8 * j)) & 0xFFu; }
#pragma unroll
    for (int j = 0; j < 4; ++j) { gb[4 + j] = (g.y >> (8 * j)) & 0xFFu; }

    float sum = 0.0f;
#pragma unroll
    for (int j = 0; j < 8; ++j) {
        float x = xv[j];
        float t = __logf(1.0f + __expf(-fabsf(x)));
        float l = gb[j] ? POS_W * (fmaxf(-x, 0.0f) + t)
                        : (fmaxf(x, 0.0f) + t);
        sum += l;
    }

    // warp reduce
#pragma unroll
    for (int off = 16; off > 0; off >>= 1)
        sum += __shfl_xor_sync(0xFFFFFFFFu, sum, off);

    __shared__ float ws[8];
    int w = threadIdx.x >> 5;
    if ((threadIdx.x & 31) == 0) ws[w] = sum;
    __syncthreads();
    if (threadIdx.x == 0) {
        float v = 0.0f;
#pragma unroll
        for (int j = 0; j < 8; ++j) v += ws[j];
        atomicAdd(&g_acc, (double)v);
        __threadfence();
        unsigned done = atomicAdd(&g_done, 1u);
        if (done == gridDim.x - 1) {
            // All other blocks' g_acc adds are fenced before their g_done
            // increments; observing the final count makes the sum visible.
            double s = *((volatile double*)&g_acc);
            out[0] = (float)(s * (1.0 / ((double)BB * (double)SS)));
            g_acc = 0.0;          // reset for next graph replay
            g_done = 0u;
        }
    }
}

extern "C" void kernel_launch(void* const* d_in, const int* in_sizes, int n_in,
                              void* d_out, int out_size) {
    // paths is uniquely the largest input (B*P*2 elements). Among the rest,
    // preds precedes targets in both dict and alphabetical orderings.
    int pi_idx = 0;
    for (int i = 1; i < n_in; ++i)
        if (in_sizes[i] > in_sizes[pi_idx]) pi_idx = i;

    const void* paths = d_in[pi_idx];
    const float* preds = nullptr;
    const int*   targets = nullptr;
    for (int i = 0; i < n_in; ++i) {
        if (i == pi_idx) continue;
        if (!preds) preds = (const float*)d_in[i];
        else        targets = (const int*)d_in[i];
    }
    float* out = (float*)d_out;

    detect_kernel<<<1, 32>>>((const unsigned*)paths);             // dtype + reset
    scatter_kernel<<<(BB * PP / 2) / 256, 256>>>(paths, targets); // 2 entries/thr
    loss_kernel<<<(BB * SS / 8) / 256, 256>>>(preds, out);        // 8 elems/thr
}

// round 10
// speedup vs baseline: 1.0581x; 1.0581x over previous
#include <cuda_runtime.h>
#include <cstdint>

#define BB 128
#define SS 32768
#define PP 65536
#define POS_W 5.0f

static_assert((PP % 512) == 0, "blocks must not span batches");

// Scratch (allocation-free rule: __device__ globals).
// g_gt is zero at module load; loss_kernel re-zeroes it every call, so the
// "cleared" invariant holds across graph replays without a dedicated kernel.
__device__ __align__(16) unsigned char g_gt[(size_t)BB * SS];  // 4 MiB
__device__ double g_acc;      // zero at load; last loss block resets each call
__device__ unsigned g_done;   // ditto

// ---------------------------------------------------------------------------
// Kernel 1: scatter, with inline per-warp dtype detection.
//
// Dtype probe: 8 odd 32-bit words at mid-batch entry positions, all within
// the first 59 MB (valid under both int32 [64 MB] and int64 [134 MB]).
//   int64 layout -> odd words are hi-halves of values < 2^15 -> all zero.
//   int32 layout -> words are pj[b][P/2] (median of 65536 sorted draws over
//                   [0,32768)) -> nonzero with overwhelming probability.
// Same 8 addresses for every warp -> L2 broadcast after the first wave.
//
// TWO path entries per thread (B*P/2 threads); identical thread->entry map in
// both branches. pj sorted per batch => is_first == (pj[k] != pj[k-1]).
// Entry 2t's prev comes via shuffle of the neighbor's second pj; lane 0 loads
// the one straggler scalar. All effective gt writers store 1 => plain byte
// store, benign race. Paths streamed __ldcs to keep targets/gt rows in L2.
// ---------------------------------------------------------------------------
__global__ void scatter_kernel(const void* __restrict__ paths_v,
                               const int* __restrict__ targets) {
    const unsigned lane = threadIdx.x & 31;

    // --- dtype probe (warp-uniform) ---
    unsigned det = 0;
    if (lane < 8) {
        size_t entry = (size_t)lane * 1048576 + 32768;   // mid-batch positions
        det = ((const unsigned*)paths_v)[entry * 2 + 1]; // odd word
    }
    const bool is32 = __any_sync(0xFFFFFFFFu, det != 0u);

    unsigned t = blockIdx.x * blockDim.x + threadIdx.x;   // < B*P/2 = 2^22
    unsigned k0 = (t & (PP / 2 - 1)) * 2;   // first entry's step within batch
    unsigned b  = t >> 15;                  // P/2 = 2^15 threads per batch

    int pi0, pj0, pi1, pj1, prev0;
    if (is32) {
        const int4* p = (const int4*)paths_v;             // 2 entries per int4
        int4 v = __ldcs(p + t);
        pi0 = v.x; pj0 = v.y; pi1 = v.z; pj1 = v.w;
        prev0 = __shfl_up_sync(0xFFFFFFFFu, pj1, 1);
        if (lane == 0)
            prev0 = (k0 == 0) ? -1
                  : ((const int*)paths_v)[(size_t)4 * t - 1];
    } else {
        const uint4* p = (const uint4*)paths_v;           // 1 entry per uint4
        uint4 v0 = __ldcs(p + (size_t)2 * t);
        uint4 v1 = __ldcs(p + (size_t)2 * t + 1);
        pi0 = (int)v0.x; pj0 = (int)v0.z;                 // low words (LE)
        pi1 = (int)v1.x; pj1 = (int)v1.z;
        prev0 = __shfl_up_sync(0xFFFFFFFFu, pj1, 1);
        if (lane == 0)
            prev0 = (k0 == 0) ? -1
                  : (int)((const long long*)paths_v)[(size_t)4 * t - 1];
    }

    const int* trow = targets + b * SS;
    unsigned char* grow = g_gt + b * SS;
    if (pj0 != prev0 && trow[pj0] == 1) grow[pi0] = (unsigned char)1;
    if (pj1 != pj0   && trow[pj1] == 1) grow[pi1] = (unsigned char)1;
}

// ---------------------------------------------------------------------------
// Kernel 2: loss + reduction + finalize + gt re-zero. 8 elements per thread
// (2x float4 preds, 8 gt bytes). loss = 5*gt*softplus(-x)+(1-gt)*softplus(x);
// softplus(x) = max(x,0) + log(1 + exp(-|x|)), MUFU fast-math (arg of log in
// [1,2] -> abs err ~1e-7, negligible vs 1e-3 threshold).
// Zeros are stored back after the gt read, restoring the cleared invariant
// for the next graph replay. Last finished block writes the mean and resets
// the accumulators.
// ---------------------------------------------------------------------------
__global__ void loss_kernel(const float* __restrict__ preds,
                            float* __restrict__ out) {
    unsigned i = blockIdx.x * blockDim.x + threadIdx.x;   // < B*S/8
    float4 p0 = ((const float4*)preds)[(size_t)2 * i];
    float4 p1 = ((const float4*)preds)[(size_t)2 * i + 1];
    uint2 g = ((const uint2*)g_gt)[i];
    ((uint2*)g_gt)[i] = make_uint2(0u, 0u);              // re-zero for next call

    float xv[8] = {p0.x, p0.y, p0.z, p0.w, p1.x, p1.y, p1.z, p1.w};
    unsigned gb[8];
#pragma unroll
    for (int j = 0; j < 4; ++j) { gb[j] = (g.x >> (8 * j)) & 0xFFu; }
#pragma unroll
    for (int j = 0; j < 4; ++j) { gb[4 + j] = (g.y >> (8 * j)) & 0xFFu; }

    float sum = 0.0f;
#pragma unroll
    for (int j = 0; j < 8; ++j) {
        float x = xv[j];
        float t = __logf(1.0f + __expf(-fabsf(x)));
        float l = gb[j] ? POS_W * (fmaxf(-x, 0.0f) + t)
                        : (fmaxf(x, 0.0f) + t);
        sum += l;
    }

    // warp reduce
#pragma unroll
    for (int off = 16; off > 0; off >>= 1)
        sum += __shfl_xor_sync(0xFFFFFFFFu, sum, off);

    __shared__ float ws[8];
    int w = threadIdx.x >> 5;
    if ((threadIdx.x & 31) == 0) ws[w] = sum;
    __syncthreads();
    if (threadIdx.x == 0) {
        float v = 0.0f;
#pragma unroll
        for (int j = 0; j < 8; ++j) v += ws[j];
        atomicAdd(&g_acc, (double)v);
        __threadfence();
        unsigned done = atomicAdd(&g_done, 1u);
        if (done == gridDim.x - 1) {
            // All other blocks' g_acc adds are fenced before their g_done
            // increments; observing the final count makes the sum visible.
            double s = *((volatile double*)&g_acc);
            out[0] = (float)(s * (1.0 / ((double)BB * (double)SS)));
            g_acc = 0.0;          // reset for next graph replay
            g_done = 0u;
        }
    }
}

extern "C" void kernel_launch(void* const* d_in, const int* in_sizes, int n_in,
                              void* d_out, int out_size) {
    // paths is uniquely the largest input (B*P*2 elements). Among the rest,
    // preds precedes targets in both dict and alphabetical orderings.
    int pi_idx = 0;
    for (int i = 1; i < n_in; ++i)
        if (in_sizes[i] > in_sizes[pi_idx]) pi_idx = i;

    const void* paths = d_in[pi_idx];
    const float* preds = nullptr;
    const int*   targets = nullptr;
    for (int i = 0; i < n_in; ++i) {
        if (i == pi_idx) continue;
        if (!preds) preds = (const float*)d_in[i];
        else        targets = (const int*)d_in[i];
    }
    float* out = (float*)d_out;

    scatter_kernel<<<(BB * PP / 2) / 256, 256>>>(paths, targets); // 2 entries/thr
    loss_kernel<<<(BB * SS / 8) / 256, 256>>>(preds, out);        // 8 elems/thr
}

// round 11
// speedup vs baseline: 1.1949x; 1.1293x over previous
#include <cuda_runtime.h>
#include <cstdint>

#define BB 128
#define SS 32768
#define PP 65536
#define POS_W 5.0f
#define NT 1024                    // threads per block
#define SCAT_ITERS (PP / 2 / NT)   // 32 (2 entries per thread per iter)
#define TGT_ITERS  (SS / NT)       // 32 (1 int per thread per iter)
#define PRED_ITERS (SS / 4 / NT)   // 8  (1 float4 per thread per iter)

static_assert(SS / 32 == NT, "gt bitmap zeroed with one word per thread");

__device__ double g_acc;      // zero at load; last block resets each call
__device__ unsigned g_done;   // ditto

// ---------------------------------------------------------------------------
// ONE kernel: one block per batch. gt lives in a 4 KB SMEM bitmap (no global
// scratch, no zero kernel, no inter-kernel deps). targets row compressed to a
// 4 KB SMEM bitmap via ballot. Blocks are fully independent; phases within a
// block are separated by __syncthreads only.
//
// Dtype probe (block-uniform, 1 broadcast load): odd 32-bit word at this
// batch's mid entry. int64 layout -> odd words are hi-halves of values <
// 2^15 -> 0. int32 layout -> that word is pj[b][P/2] (median of 65536 sorted
// draws over [0,32768)) -> nonzero. Max word index 16,711,681 < 16,777,216,
// in-bounds under both interpretations.
//
// Scatter: pj sorted per batch => is_first == (pj[k] != pj[k-1]). Entry pair
// per thread; prev of the pair's first entry comes from the neighbor lane's
// second pj (shuffle); lane 0 loads the one straggler scalar (L2-hot).
// Effective writers OR a 1-bit => smem atomicOr, spread addresses.
//
// Loss: softplus(x) = max(x,0) + log(1+exp(-|x|)) with MUFU fast-math (arg
// of log in [1,2] -> abs err ~1e-7, negligible vs the 1e-3 threshold).
// Block sums -> one double atomicAdd; 128th block writes the mean & resets.
// ---------------------------------------------------------------------------
__global__ void __launch_bounds__(NT, 1)
fused_kernel(const void* __restrict__ paths_v,
             const int* __restrict__ targets,
             const float* __restrict__ preds,
             float* __restrict__ out) {
    __shared__ unsigned tbit[SS / 32];   // targets bitmap, 4 KB
    __shared__ unsigned gbit[SS / 32];   // gt bitmap, 4 KB
    __shared__ float ws[NT / 32];

    const unsigned b    = blockIdx.x;
    const unsigned tid  = threadIdx.x;
    const unsigned lane = tid & 31;
    const unsigned wrp  = tid >> 5;

    gbit[tid] = 0u;                      // SS/32 == NT: one word per thread

    // --- dtype probe (block-uniform branch) ---
    const size_t mid_entry = (size_t)b * PP + PP / 2;
    const bool is32 =
        ((const unsigned*)paths_v)[mid_entry * 2 + 1] != 0u;

    // --- Phase A: targets row -> bitmap (coalesced + ballot) ---
    const int* trow = targets + (size_t)b * SS;
    for (int k = 0; k < TGT_ITERS; ++k) {
        unsigned e = k * NT + tid;                     // one int per thread
        unsigned m = __ballot_sync(0xFFFFFFFFu, trow[e] == 1);
        if (lane == 0) tbit[e >> 5] = m;
    }
    __syncthreads();

    // --- Phase B: scatter into smem gt bitmap ---
    if (is32) {
        const int4* p = (const int4*)paths_v + (size_t)b * (PP / 2);
#pragma unroll 4
        for (int i = 0; i < SCAT_ITERS; ++i) {
            unsigned t = i * NT + tid;                 // entry-pair index
            int4 v = __ldcs(p + t);
            int pi0 = v.x, pj0 = v.y, pi1 = v.z, pj1 = v.w;
            int prev0 = __shfl_up_sync(0xFFFFFFFFu, pj1, 1);
            if (lane == 0)
                prev0 = (t == 0) ? -1
                      : ((const int*)paths_v)[(size_t)b * PP * 2 + 4 * t - 1];
            if (pj0 != prev0 && ((tbit[pj0 >> 5] >> (pj0 & 31)) & 1u))
                atomicOr(&gbit[pi0 >> 5], 1u << (pi0 & 31));
            if (pj1 != pj0 && ((tbit[pj1 >> 5] >> (pj1 & 31)) & 1u))
                atomicOr(&gbit[pi1 >> 5], 1u << (pi1 & 31));
        }
    } else {
        const uint4* p = (const uint4*)paths_v + (size_t)b * PP;
#pragma unroll 4
        for (int i = 0; i < SCAT_ITERS; ++i) {
            unsigned t = i * NT + tid;                 // entry-pair index
            uint4 v0 = __ldcs(p + (size_t)2 * t);
            uint4 v1 = __ldcs(p + (size_t)2 * t + 1);
            int pi0 = (int)v0.x, pj0 = (int)v0.z;      // low words (LE)
            int pi1 = (int)v1.x, pj1 = (int)v1.z;
            int prev0 = __shfl_up_sync(0xFFFFFFFFu, pj1, 1);
            if (lane == 0)
                prev0 = (t == 0) ? -1
                      : (int)((const unsigned*)paths_v)
                            [((size_t)b * PP + 2 * t - 1) * 4 + 2]; // pj lo word
            if (pj0 != prev0 && ((tbit[pj0 >> 5] >> (pj0 & 31)) & 1u))
                atomicOr(&gbit[pi0 >> 5], 1u << (pi0 & 31));
            if (pj1 != pj0 && ((tbit[pj1 >> 5] >> (pj1 & 31)) & 1u))
                atomicOr(&gbit[pi1 >> 5], 1u << (pi1 & 31));
        }
    }
    __syncthreads();

    // --- Phase C: loss over this batch's preds row ---
    const float4* prow = (const float4*)(preds + (size_t)b * SS);
    float sum = 0.0f;
#pragma unroll
    for (int i = 0; i < PRED_ITERS; ++i) {
        unsigned e4 = i * NT + tid;                    // float4 index
        float4 x = prow[e4];
        unsigned gw = gbit[e4 >> 3];                   // 8 float4s per word
        unsigned sh = (e4 & 7u) * 4u;                  // our 4 bits
        float xv[4] = {x.x, x.y, x.z, x.w};
#pragma unroll
        for (int j = 0; j < 4; ++j) {
            float v = xv[j];
            float t = __logf(1.0f + __expf(-fabsf(v)));
            bool gt = (gw >> (sh + j)) & 1u;
            sum += gt ? POS_W * (fmaxf(-v, 0.0f) + t)
                      : (fmaxf(v, 0.0f) + t);
        }
    }

    // block reduce
#pragma unroll
    for (int off = 16; off > 0; off >>= 1)
        sum += __shfl_xor_sync(0xFFFFFFFFu, sum, off);
    if (lane == 0) ws[wrp] = sum;
    __syncthreads();
    if (tid < 32) {
        float v = (tid < NT / 32) ? ws[tid] : 0.0f;
#pragma unroll
        for (int off = 16; off > 0; off >>= 1)
            v += __shfl_xor_sync(0xFFFFFFFFu, v, off);
        if (tid == 0) {
            atomicAdd(&g_acc, (double)v);
            __threadfence();
            unsigned done = atomicAdd(&g_done, 1u);
            if (done == gridDim.x - 1) {
                // Every other block's g_acc add is fenced before its g_done
                // increment; observing the final count makes the sum visible.
                double s = *((volatile double*)&g_acc);
                out[0] = (float)(s * (1.0 / ((double)BB * (double)SS)));
                g_acc = 0.0;      // reset for next graph replay
                g_done = 0u;
            }
        }
    }
}

extern "C" void kernel_launch(void* const* d_in, const int* in_sizes, int n_in,
                              void* d_out, int out_size) {
    // paths is uniquely the largest input (B*P*2 elements). Among the rest,
    // preds precedes targets in both dict and alphabetical orderings.
    int pi_idx = 0;
    for (int i = 1; i < n_in; ++i)
        if (in_sizes[i] > in_sizes[pi_idx]) pi_idx = i;

    const void* paths = d_in[pi_idx];
    const float* preds = nullptr;
    const int*   targets = nullptr;
    for (int i = 0; i < n_in; ++i) {
        if (i == pi_idx) continue;
        if (!preds) preds = (const float*)d_in[i];
        else        targets = (const int*)d_in[i];
    }
    float* out = (float*)d_out;

    fused_kernel<<<BB, NT>>>(paths, targets, preds, out);
}

// round 12
// speedup vs baseline: 1.2629x; 1.0569x over previous
#include <cuda_runtime.h>
#include <cstdint>

#define BB 128
#define SS 32768
#define PP 65536
#define POS_W 5.0f

// Scratch (allocation-free rule: __device__ globals).
// g_bit: 512 KB gt bitmap — L2-resident. Zero at module load; loss_kernel
// re-zeroes each word after reading it, restoring the invariant per replay.
__device__ unsigned g_bit[(size_t)BB * SS / 32];
__device__ double g_acc;      // zero at load; last loss block resets each call
__device__ unsigned g_done;   // ditto

// ---------------------------------------------------------------------------
// Kernel 1: scatter. FOUR entries per thread (B*P/4 = 2,097,152 threads),
// full-chip grid, no phases -> maximal MLP against the 64 MB paths stream.
//
// Per-warp dtype probe: 8 odd 32-bit words at mid-batch entry positions
// (max word 14,745,665 < 16,777,216 -> in-bounds under int32 and int64).
// int64 layout -> odd words are hi-halves of values < 2^15 -> all zero.
// int32 layout -> words are mid-batch pj values (nonzero a.s.).
//
// pj sorted per batch => is_first == (pj[k] != pj[k-1]). prev for entries
// 1..3 is in-register; entry 0's prev comes from the neighbor lane's pj[3]
// (shuffle); lane 0 loads the one straggler scalar (L2-hot).
// hit => atomicOr of one bit into the L2-resident bitmap (REDG, spread).
// ---------------------------------------------------------------------------
__global__ void scatter_kernel(const void* __restrict__ paths_v,
                               const int* __restrict__ targets) {
    const unsigned lane = threadIdx.x & 31;

    // --- dtype probe (warp-uniform) ---
    unsigned det = 0;
    if (lane < 8) {
        size_t entry = ((size_t)lane << 20) + 32768;     // mid-batch positions
        det = ((const unsigned*)paths_v)[entry * 2 + 1]; // odd word
    }
    const bool is32 = __any_sync(0xFFFFFFFFu, det != 0u);

    unsigned t = blockIdx.x * blockDim.x + threadIdx.x;  // < B*P/4 = 2^21
    unsigned k0 = (t & 16383) * 4;     // first entry's step within batch
    unsigned b  = t >> 14;             // P/4 = 2^14 threads per batch

    int pi[4], pj[4];
    if (is32) {
        const int4* p = (const int4*)paths_v + (size_t)2 * t;  // 2 entries/int4
        int4 v0 = __ldcs(p);
        int4 v1 = __ldcs(p + 1);
        pi[0] = v0.x; pj[0] = v0.y; pi[1] = v0.z; pj[1] = v0.w;
        pi[2] = v1.x; pj[2] = v1.y; pi[3] = v1.z; pj[3] = v1.w;
    } else {
        const uint4* p = (const uint4*)paths_v + (size_t)4 * t; // 1 entry/uint4
        uint4 v0 = __ldcs(p);
        uint4 v1 = __ldcs(p + 1);
        uint4 v2 = __ldcs(p + 2);
        uint4 v3 = __ldcs(p + 3);
        pi[0] = (int)v0.x; pj[0] = (int)v0.z;            // low words (LE)
        pi[1] = (int)v1.x; pj[1] = (int)v1.z;
        pi[2] = (int)v2.x; pj[2] = (int)v2.z;
        pi[3] = (int)v3.x; pj[3] = (int)v3.z;
    }

    int prev = __shfl_up_sync(0xFFFFFFFFu, pj[3], 1);
    if (lane == 0) {
        if (k0 == 0) prev = -1;
        else prev = is32
            ? ((const int*)paths_v)[((size_t)b * PP + k0 - 1) * 2 + 1]
            : (int)((const unsigned*)paths_v)[((size_t)b * PP + k0 - 1) * 4 + 2];
    }

    const int* trow = targets + (size_t)b * SS;
    unsigned* brow = g_bit + (size_t)b * (SS / 32);
#pragma unroll
    for (int j = 0; j < 4; ++j) {
        if (pj[j] != prev && trow[pj[j]] == 1)
            atomicOr(&brow[pi[j] >> 5], 1u << (pi[j] & 31));
        prev = pj[j];
    }
}

// ---------------------------------------------------------------------------
// Kernel 2: loss + reduction + finalize + bitmap re-zero. 8 elements per
// thread (2x float4 preds + 8 gt bits). 4 threads share one bitmap word
// (32 B per warp, one L2 sector); after all lanes read, the designated lane
// stores 0 (syncwarp-ordered), restoring the cleared invariant.
// loss = 5*gt*softplus(-x)+(1-gt)*softplus(x);
// softplus(x) = max(x,0) + log(1+exp(-|x|)), MUFU fast-math (arg of log in
// [1,2] -> abs err ~1e-7, negligible vs the 1e-3 threshold).
// Last finished block writes the mean and resets the accumulators.
// ---------------------------------------------------------------------------
__global__ void loss_kernel(const float* __restrict__ preds,
                            float* __restrict__ out) {
    unsigned i = blockIdx.x * blockDim.x + threadIdx.x;   // < B*S/8 = 2^19
    float4 p0 = ((const float4*)preds)[(size_t)2 * i];
    float4 p1 = ((const float4*)preds)[(size_t)2 * i + 1];

    unsigned wrd = i >> 2;                // word (8i)>>5 ; 4 threads per word
    unsigned gw = g_bit[wrd];
    __syncwarp();
    if ((i & 3) == 0) g_bit[wrd] = 0u;    // re-zero for next replay
    unsigned sh = (i & 3u) * 8u;          // our 8 bits within the word

    float xv[8] = {p0.x, p0.y, p0.z, p0.w, p1.x, p1.y, p1.z, p1.w};
    float sum = 0.0f;
#pragma unroll
    for (int j = 0; j < 8; ++j) {
        float x = xv[j];
        float t = __logf(1.0f + __expf(-fabsf(x)));
        bool gt = (gw >> (sh + j)) & 1u;
        sum += gt ? POS_W * (fmaxf(-x, 0.0f) + t)
                  : (fmaxf(x, 0.0f) + t);
    }

    // warp reduce
#pragma unroll
    for (int off = 16; off > 0; off >>= 1)
        sum += __shfl_xor_sync(0xFFFFFFFFu, sum, off);

    __shared__ float ws[8];
    int w = threadIdx.x >> 5;
    if ((threadIdx.x & 31) == 0) ws[w] = sum;
    __syncthreads();
    if (threadIdx.x == 0) {
        float v = 0.0f;
#pragma unroll
        for (int j = 0; j < 8; ++j) v += ws[j];
        atomicAdd(&g_acc, (double)v);
        __threadfence();
        unsigned done = atomicAdd(&g_done, 1u);
        if (done == gridDim.x - 1) {
            // Every other block's g_acc add is fenced before its g_done
            // increment; observing the final count makes the sum visible.
            double s = *((volatile double*)&g_acc);
            out[0] = (float)(s * (1.0 / ((double)BB * (double)SS)));
            g_acc = 0.0;          // reset for next graph replay
            g_done = 0u;
        }
    }
}

extern "C" void kernel_launch(void* const* d_in, const int* in_sizes, int n_in,
                              void* d_out, int out_size) {
    // paths is uniquely the largest input (B*P*2 elements). Among the rest,
    // preds precedes targets in both dict and alphabetical orderings.
    int pi_idx = 0;
    for (int i = 1; i < n_in; ++i)
        if (in_sizes[i] > in_sizes[pi_idx]) pi_idx = i;

    const void* paths = d_in[pi_idx];
    const float* preds = nullptr;
    const int*   targets = nullptr;
    for (int i = 0; i < n_in; ++i) {
        if (i == pi_idx) continue;
        if (!preds) preds = (const float*)d_in[i];
        else        targets = (const int*)d_in[i];
    }
    float* out = (float*)d_out;

    scatter_kernel<<<(BB * PP / 4) / 256, 256>>>(paths, targets); // 4 entr/thr
    loss_kernel<<<(BB * SS / 8) / 256, 256>>>(preds, out);        // 8 elems/thr
}